// round 3
// baseline (speedup 1.0000x reference)
#include <cuda_runtime.h>

#define CCH 256
#define HH 256
#define WW 256
#define PLANE (HH * WW)
#define TH 16
#define TW 32
#define HALO_H 22                 // TH + 6 rows
#define SMW 40                    // smem row width in floats (halo width, 8B-aligned window)
#define SMW2 (SMW / 2)            // 20 float2 per row
#define HALO_N2 (HALO_H * SMW2)   // 440 float2 per buffer
#define NSLOT 2
#define NTHREADS 256
#define EPSF 1e-12f

__global__ __launch_bounds__(NTHREADS, 1)
void corr_kernel(const float* __restrict__ x,
                 const float* __restrict__ y,
                 float* __restrict__ out)
{
    // double-buffered y halo
    __shared__ __align__(16) float sy[2][HALO_H * SMW];

    const int tid = threadIdx.x;
    const int tx  = tid & 7;          // 0..7, each owns 4 w-pixels
    const int ty  = (tid >> 3) & 15;  // 0..15
    const int grp = tid >> 7;         // 0: i-offsets 0..3,  1: i-offsets 4..6
    const int i0  = grp ? 4 : 0;
    const int b   = blockIdx.z;
    const int h0  = blockIdx.y * TH;
    const int w0  = blockIdx.x * TW;
    const int h   = h0 + ty;

    // staging precompute: halo gy in [h0-3, h0+18], gx in [w0-4, w0+35]
    // even gx start -> aligned float2 global loads, pairs never straddle the edge.
    int g2of[NSLOT];
    unsigned mask = 0;
    #pragma unroll
    for (int k = 0; k < NSLOT; k++) {
        int idx = tid + k * NTHREADS;
        int r   = idx / SMW2;
        int cc  = idx - r * SMW2;
        int gy  = h0 - 3 + r;
        int gx  = w0 - 4 + 2 * cc;
        g2of[k] = gy * (WW / 2) + (gx >> 1);
        bool wr  = idx < HALO_N2;
        bool vld = wr && gy >= 0 && gy < HH && gx >= 0 && gx < WW;
        if (wr)  mask |= 1u << k;
        if (vld) mask |= 0x100u << k;
    }

    const float4* xp = reinterpret_cast<const float4*>(
        x + (((size_t)b * CCH) * HH + h) * WW + w0 + tx * 4);
    const float2* yb = reinterpret_cast<const float2*>(y) +
        (size_t)b * CCH * (PLANE / 2);

    float acc[4][7][4];
    #pragma unroll
    for (int i = 0; i < 4; i++)
        #pragma unroll
        for (int j = 0; j < 7; j++)
            #pragma unroll
            for (int p = 0; p < 4; p++)
                acc[i][j][p] = 0.f;

    float sxx[4] = {0.f, 0.f, 0.f, 0.f};
    float2 syy[NSLOT];
    #pragma unroll
    for (int k = 0; k < NSLOT; k++) syy[k] = make_float2(0.f, 0.f);

    // ---- prologue: stage channel 0 into buffer 0
    #pragma unroll
    for (int k = 0; k < NSLOT; k++) {
        if (mask & (1u << k)) {
            float2 v = make_float2(0.f, 0.f);
            if (mask & (0x100u << k)) v = __ldg(yb + g2of[k]);
            reinterpret_cast<float2*>(sy[0])[tid + k * NTHREADS] = v;
            syy[k].x = fmaf(v.x, v.x, syy[k].x);
            syy[k].y = fmaf(v.y, v.y, syy[k].y);
        }
    }
    __syncthreads();

    // ================= channel loop (1 barrier per channel) =================
    #pragma unroll 1
    for (int c = 0; c < CCH; c++) {
        const int cur = c & 1;

        // prefetch: stage channel c+1 into the other buffer
        if (c + 1 < CCH) {
            const float2* ypc = yb + (size_t)(c + 1) * (PLANE / 2);
            #pragma unroll
            for (int k = 0; k < NSLOT; k++) {
                if (mask & (1u << k)) {
                    float2 v = make_float2(0.f, 0.f);
                    if (mask & (0x100u << k)) v = __ldg(ypc + g2of[k]);
                    reinterpret_cast<float2*>(sy[cur ^ 1])[tid + k * NTHREADS] = v;
                    syy[k].x = fmaf(v.x, v.x, syy[k].x);
                    syy[k].y = fmaf(v.y, v.y, syy[k].y);
                }
            }
        }

        const float4 xv = __ldg(xp);
        xp += PLANE / 4;
        sxx[0] = fmaf(xv.x, xv.x, sxx[0]);
        sxx[1] = fmaf(xv.y, xv.y, sxx[1]);
        sxx[2] = fmaf(xv.z, xv.z, sxx[2]);
        sxx[3] = fmaf(xv.w, xv.w, sxx[3]);

        const float* base = sy[cur] + (ty + i0) * SMW + tx * 4;

        // 3 rows unconditionally (both groups), 4th row only for group A
        #pragma unroll
        for (int i = 0; i < 3; i++) {
            const float* row = base + i * SMW;
            float4 t0 = *reinterpret_cast<const float4*>(row);
            float4 t1 = *reinterpret_cast<const float4*>(row + 4);
            float4 t2 = *reinterpret_cast<const float4*>(row + 8);
            float yr[12];
            yr[0] = t0.x; yr[1]  = t0.y; yr[2]  = t0.z; yr[3]  = t0.w;
            yr[4] = t1.x; yr[5]  = t1.y; yr[6]  = t1.z; yr[7]  = t1.w;
            yr[8] = t2.x; yr[9]  = t2.y; yr[10] = t2.z; yr[11] = t2.w;
            #pragma unroll
            for (int j = 0; j < 7; j++) {
                acc[i][j][0] = fmaf(xv.x, yr[j + 1], acc[i][j][0]);
                acc[i][j][1] = fmaf(xv.y, yr[j + 2], acc[i][j][1]);
                acc[i][j][2] = fmaf(xv.z, yr[j + 3], acc[i][j][2]);
                acc[i][j][3] = fmaf(xv.w, yr[j + 4], acc[i][j][3]);
            }
        }
        if (grp == 0) {   // warp-uniform branch (warps 0-3)
            const float* row = base + 3 * SMW;
            float4 t0 = *reinterpret_cast<const float4*>(row);
            float4 t1 = *reinterpret_cast<const float4*>(row + 4);
            float4 t2 = *reinterpret_cast<const float4*>(row + 8);
            float yr[12];
            yr[0] = t0.x; yr[1]  = t0.y; yr[2]  = t0.z; yr[3]  = t0.w;
            yr[4] = t1.x; yr[5]  = t1.y; yr[6]  = t1.z; yr[7]  = t1.w;
            yr[8] = t2.x; yr[9]  = t2.y; yr[10] = t2.z; yr[11] = t2.w;
            #pragma unroll
            for (int j = 0; j < 7; j++) {
                acc[3][j][0] = fmaf(xv.x, yr[j + 1], acc[3][j][0]);
                acc[3][j][1] = fmaf(xv.y, yr[j + 2], acc[3][j][1]);
                acc[3][j][2] = fmaf(xv.z, yr[j + 3], acc[3][j][2]);
                acc[3][j][3] = fmaf(xv.w, yr[j + 4], acc[3][j][3]);
            }
        }
        __syncthreads();
    }

    // ================= epilogue: normalize =================
    // publish per-pixel sum(y^2) through buffer 0
    #pragma unroll
    for (int k = 0; k < NSLOT; k++)
        if (mask & (1u << k))
            reinterpret_cast<float2*>(sy[0])[tid + k * NTHREADS] = syy[k];
    __syncthreads();

    float invx[4];
    #pragma unroll
    for (int p = 0; p < 4; p++)
        invx[p] = 1.0f / fmaxf(sqrtf(sxx[p]), EPSF);

    const int nrows = grp ? 3 : 4;
    float* op = out + ((size_t)b * 49) * PLANE + (size_t)h * WW + w0 + tx * 4;
    #pragma unroll
    for (int i = 0; i < 4; i++) {
        if (i < nrows) {
            const int iglob = i0 + i;
            const float* row = sy[0] + (ty + iglob) * SMW + tx * 4;
            float inr[11];
            #pragma unroll
            for (int t = 1; t <= 10; t++)
                inr[t] = 1.0f / fmaxf(sqrtf(row[t]), EPSF);
            #pragma unroll
            for (int j = 0; j < 7; j++) {
                float4 o4;
                o4.x = acc[i][j][0] * invx[0] * inr[j + 1];
                o4.y = acc[i][j][1] * invx[1] * inr[j + 2];
                o4.z = acc[i][j][2] * invx[2] * inr[j + 3];
                o4.w = acc[i][j][3] * invx[3] * inr[j + 4];
                *reinterpret_cast<float4*>(op + (size_t)(iglob * 7 + j) * PLANE) = o4;
            }
        }
    }
}

extern "C" void kernel_launch(void* const* d_in, const int* in_sizes, int n_in,
                              void* d_out, int out_size) {
    const float* x = (const float*)d_in[0];
    const float* y = (const float*)d_in[1];
    float* out = (float*)d_out;
    int B = in_sizes[0] / (CCH * HH * WW);   // = 4
    dim3 grid(WW / TW, HH / TH, B);
    corr_kernel<<<grid, NTHREADS>>>(x, y, out);
}

// round 4
// speedup vs baseline: 1.6924x; 1.6924x over previous
#include <cuda_runtime.h>

#define CCH 256
#define HH 256
#define WW 256
#define PLANE (HH * WW)
#define TH 16
#define TW 32
#define HALO_H 22                 // TH + 6 rows
#define SMW 40                    // smem row width in floats (halo width, 8B-aligned window)
#define SMW2 (SMW / 2)            // 20 float2 per row
#define HALO_N2 (HALO_H * SMW2)   // 440 float2 per buffer
#define NSLOT 2
#define NTHREADS 256
#define EPSF 1e-12f

__global__ __launch_bounds__(NTHREADS, 1)
void corr_kernel(const float* __restrict__ x,
                 const float* __restrict__ y,
                 float* __restrict__ out)
{
    // double-buffered y halo
    __shared__ __align__(16) float sy[2][HALO_H * SMW];

    const int tid = threadIdx.x;
    const int tx  = tid & 7;          // 0..7, each owns 4 w-pixels
    const int ty  = (tid >> 3) & 15;  // 0..15
    const int grp = tid >> 7;         // 0: i-offsets 0..3,  1: i-offsets 4..6
    const int i0  = grp ? 4 : 0;
    const int b   = blockIdx.z;
    const int h0  = blockIdx.y * TH;
    const int w0  = blockIdx.x * TW;
    const int h   = h0 + ty;

    // staging precompute: halo gy in [h0-3, h0+18], gx in [w0-4, w0+35]
    // even gx start -> aligned float2 global loads, pairs never straddle the edge.
    int g2of[NSLOT];
    unsigned mask = 0;
    #pragma unroll
    for (int k = 0; k < NSLOT; k++) {
        int idx = tid + k * NTHREADS;
        int r   = idx / SMW2;
        int cc  = idx - r * SMW2;
        int gy  = h0 - 3 + r;
        int gx  = w0 - 4 + 2 * cc;
        g2of[k] = gy * (WW / 2) + (gx >> 1);
        bool wr  = idx < HALO_N2;
        bool vld = wr && gy >= 0 && gy < HH && gx >= 0 && gx < WW;
        if (wr)  mask |= 1u << k;
        if (vld) mask |= 0x100u << k;
    }

    const float4* xp = reinterpret_cast<const float4*>(
        x + (((size_t)b * CCH) * HH + h) * WW + w0 + tx * 4);
    const float2* yb = reinterpret_cast<const float2*>(y) +
        (size_t)b * CCH * (PLANE / 2);

    float acc[4][7][4];
    #pragma unroll
    for (int i = 0; i < 4; i++)
        #pragma unroll
        for (int j = 0; j < 7; j++)
            #pragma unroll
            for (int p = 0; p < 4; p++)
                acc[i][j][p] = 0.f;

    float sxx[4] = {0.f, 0.f, 0.f, 0.f};
    float2 syy[NSLOT];
    #pragma unroll
    for (int k = 0; k < NSLOT; k++) syy[k] = make_float2(0.f, 0.f);

    // ---- prologue: stage channel 0 into buffer 0, prefetch x(ch0)
    #pragma unroll
    for (int k = 0; k < NSLOT; k++) {
        if (mask & (1u << k)) {
            float2 v = make_float2(0.f, 0.f);
            if (mask & (0x100u << k)) v = __ldg(yb + g2of[k]);
            reinterpret_cast<float2*>(sy[0])[tid + k * NTHREADS] = v;
            syy[k].x = fmaf(v.x, v.x, syy[k].x);
            syy[k].y = fmaf(v.y, v.y, syy[k].y);
        }
    }
    float4 xv = __ldg(xp);
    xp += PLANE / 4;
    __syncthreads();

    // ================= channel loop =================
    // pipeline: issue LDGs for c+1  ->  FMA block for c (hides latency)
    //           ->  STS prefetch into other buffer  ->  barrier
    #pragma unroll 1
    for (int c = 0; c < CCH; c++) {
        const int cur  = c & 1;
        const bool pf  = (c + 1 < CCH);

        // issue next-channel loads into registers (no consumer until after compute)
        float2 pv[NSLOT];
        float4 xnext = xv;
        if (pf) {
            const float2* ypc = yb + (size_t)(c + 1) * (PLANE / 2);
            #pragma unroll
            for (int k = 0; k < NSLOT; k++) {
                pv[k] = make_float2(0.f, 0.f);
                if (mask & (0x100u << k)) pv[k] = __ldg(ypc + g2of[k]);
            }
            xnext = __ldg(xp);
            xp += PLANE / 4;
        }

        // ---- compute channel c from sy[cur]
        sxx[0] = fmaf(xv.x, xv.x, sxx[0]);
        sxx[1] = fmaf(xv.y, xv.y, sxx[1]);
        sxx[2] = fmaf(xv.z, xv.z, sxx[2]);
        sxx[3] = fmaf(xv.w, xv.w, sxx[3]);

        const float* base = sy[cur] + (ty + i0) * SMW + tx * 4;

        #pragma unroll
        for (int i = 0; i < 3; i++) {
            const float* row = base + i * SMW;
            float4 t0 = *reinterpret_cast<const float4*>(row);
            float4 t1 = *reinterpret_cast<const float4*>(row + 4);
            float4 t2 = *reinterpret_cast<const float4*>(row + 8);
            float yr[12];
            yr[0] = t0.x; yr[1]  = t0.y; yr[2]  = t0.z; yr[3]  = t0.w;
            yr[4] = t1.x; yr[5]  = t1.y; yr[6]  = t1.z; yr[7]  = t1.w;
            yr[8] = t2.x; yr[9]  = t2.y; yr[10] = t2.z; yr[11] = t2.w;
            #pragma unroll
            for (int j = 0; j < 7; j++) {
                acc[i][j][0] = fmaf(xv.x, yr[j + 1], acc[i][j][0]);
                acc[i][j][1] = fmaf(xv.y, yr[j + 2], acc[i][j][1]);
                acc[i][j][2] = fmaf(xv.z, yr[j + 3], acc[i][j][2]);
                acc[i][j][3] = fmaf(xv.w, yr[j + 4], acc[i][j][3]);
            }
        }
        if (grp == 0) {   // warp-uniform branch (warps 0-3)
            const float* row = base + 3 * SMW;
            float4 t0 = *reinterpret_cast<const float4*>(row);
            float4 t1 = *reinterpret_cast<const float4*>(row + 4);
            float4 t2 = *reinterpret_cast<const float4*>(row + 8);
            float yr[12];
            yr[0] = t0.x; yr[1]  = t0.y; yr[2]  = t0.z; yr[3]  = t0.w;
            yr[4] = t1.x; yr[5]  = t1.y; yr[6]  = t1.z; yr[7]  = t1.w;
            yr[8] = t2.x; yr[9]  = t2.y; yr[10] = t2.z; yr[11] = t2.w;
            #pragma unroll
            for (int j = 0; j < 7; j++) {
                acc[3][j][0] = fmaf(xv.x, yr[j + 1], acc[3][j][0]);
                acc[3][j][1] = fmaf(xv.y, yr[j + 2], acc[3][j][1]);
                acc[3][j][2] = fmaf(xv.z, yr[j + 3], acc[3][j][2]);
                acc[3][j][3] = fmaf(xv.w, yr[j + 4], acc[3][j][3]);
            }
        }

        // ---- commit prefetch into the other buffer (reads of it drained at
        //      the barrier that ended iteration c-1)
        if (pf) {
            #pragma unroll
            for (int k = 0; k < NSLOT; k++) {
                if (mask & (1u << k)) {
                    reinterpret_cast<float2*>(sy[cur ^ 1])[tid + k * NTHREADS] = pv[k];
                    syy[k].x = fmaf(pv[k].x, pv[k].x, syy[k].x);
                    syy[k].y = fmaf(pv[k].y, pv[k].y, syy[k].y);
                }
            }
        }
        xv = xnext;
        __syncthreads();
    }

    // ================= epilogue: normalize =================
    // publish per-pixel sum(y^2) through buffer 0
    #pragma unroll
    for (int k = 0; k < NSLOT; k++)
        if (mask & (1u << k))
            reinterpret_cast<float2*>(sy[0])[tid + k * NTHREADS] = syy[k];
    __syncthreads();

    float invx[4];
    #pragma unroll
    for (int p = 0; p < 4; p++)
        invx[p] = 1.0f / fmaxf(sqrtf(sxx[p]), EPSF);

    const int nrows = grp ? 3 : 4;
    float* op = out + ((size_t)b * 49) * PLANE + (size_t)h * WW + w0 + tx * 4;
    #pragma unroll
    for (int i = 0; i < 4; i++) {
        if (i < nrows) {
            const int iglob = i0 + i;
            const float* row = sy[0] + (ty + iglob) * SMW + tx * 4;
            float inr[11];
            #pragma unroll
            for (int t = 1; t <= 10; t++)
                inr[t] = 1.0f / fmaxf(sqrtf(row[t]), EPSF);
            #pragma unroll
            for (int j = 0; j < 7; j++) {
                float4 o4;
                o4.x = acc[i][j][0] * invx[0] * inr[j + 1];
                o4.y = acc[i][j][1] * invx[1] * inr[j + 2];
                o4.z = acc[i][j][2] * invx[2] * inr[j + 3];
                o4.w = acc[i][j][3] * invx[3] * inr[j + 4];
                *reinterpret_cast<float4*>(op + (size_t)(iglob * 7 + j) * PLANE) = o4;
            }
        }
    }
}

extern "C" void kernel_launch(void* const* d_in, const int* in_sizes, int n_in,
                              void* d_out, int out_size) {
    const float* x = (const float*)d_in[0];
    const float* y = (const float*)d_in[1];
    float* out = (float*)d_out;
    int B = in_sizes[0] / (CCH * HH * WW);   // = 4
    dim3 grid(WW / TW, HH / TH, B);
    corr_kernel<<<grid, NTHREADS>>>(x, y, out);
}

// round 5
// speedup vs baseline: 3.3361x; 1.9713x over previous
#include <cuda_runtime.h>
#include <cstdint>

#define CCH 256
#define HH 256
#define WW 256
#define PLANE (HH * WW)
#define TH 8
#define TW 32
#define HALO_H 14                 // TH + 6
#define SMW 40                    // halo width in floats (8B-aligned window)
#define SMW2 (SMW / 2)            // 20 float2 per row
#define HALO_N2 (HALO_H * SMW2)   // 280 float2 per channel slab
#define SLAB (HALO_H * SMW)       // 560 floats per channel slab
#define CPB 4                     // channels per barrier
#define NGRP (CCH / CPB)          // 64 groups
#define NSLOT 3                   // ceil(280 / 128) staging slots per thread
#define NTHREADS 128
#define EPSF 1e-12f

__device__ __forceinline__ unsigned smem_u32(const void* p) {
    return (unsigned)__cvta_generic_to_shared(p);
}
__device__ __forceinline__ void cp_async8(unsigned dst, const float2* src, unsigned sz) {
    asm volatile("cp.async.ca.shared.global [%0], [%1], 8, %2;\n"
                 :: "r"(dst), "l"(src), "r"(sz));
}
__device__ __forceinline__ void cp_commit() {
    asm volatile("cp.async.commit_group;\n");
}
__device__ __forceinline__ void cp_wait0() {
    asm volatile("cp.async.wait_group 0;\n");
}

__global__ __launch_bounds__(NTHREADS, 2)
void corr_kernel(const float* __restrict__ x,
                 const float* __restrict__ y,
                 float* __restrict__ out)
{
    // double-buffered, 4 channel slabs per buffer
    __shared__ __align__(16) float sy[2][CPB][SLAB];

    const int tid = threadIdx.x;
    const int tx  = tid & 7;          // 0..7, each owns 4 w-pixels
    const int ty  = (tid >> 3) & 7;   // 0..7
    const int grp = tid >> 6;         // 0: rows 0..3,  1: rows 4..6
    const int i0  = grp ? 4 : 0;
    const int b   = blockIdx.z;
    const int h0  = blockIdx.y * TH;
    const int w0  = blockIdx.x * TW;
    const int h   = h0 + ty;

    // staging slots: halo gy in [h0-3, h0+10], gx in [w0-4, w0+35], even gx start
    int      g2of[NSLOT];
    unsigned ssz[NSLOT];
    bool     wr[NSLOT];
    #pragma unroll
    for (int k = 0; k < NSLOT; k++) {
        int li = tid + k * NTHREADS;
        int r  = li / SMW2;
        int c2 = li - r * SMW2;
        int gy = h0 - 3 + r;
        int gx = w0 - 4 + 2 * c2;
        wr[k]  = li < HALO_N2;
        bool v = wr[k] && gy >= 0 && gy < HH && gx >= 0 && gx < WW;
        g2of[k] = v ? (gy * (WW / 2) + (gx >> 1)) : 0;
        ssz[k]  = v ? 8u : 0u;
    }

    const float4* xp = reinterpret_cast<const float4*>(
        x + (((size_t)b * CCH) * HH + h) * WW + w0 + tx * 4);
    const float2* yc = reinterpret_cast<const float2*>(y) +
        (size_t)b * CCH * (PLANE / 2);

    float acc[4][7][4];
    #pragma unroll
    for (int i = 0; i < 4; i++)
        #pragma unroll
        for (int j = 0; j < 7; j++)
            #pragma unroll
            for (int p = 0; p < 4; p++)
                acc[i][j][p] = 0.f;

    float  sxx[4] = {0.f, 0.f, 0.f, 0.f};
    float2 syy[NSLOT];
    #pragma unroll
    for (int k = 0; k < NSLOT; k++) syy[k] = make_float2(0.f, 0.f);

    float4 xv[CPB];

    // ---- prologue: stage group 0 (channels 0..3) into buffer 0
    #pragma unroll
    for (int cc = 0; cc < CPB; cc++) {
        unsigned dbase = smem_u32(&sy[0][cc][0]);
        #pragma unroll
        for (int k = 0; k < NSLOT; k++)
            if (wr[k]) cp_async8(dbase + (unsigned)(tid + k * NTHREADS) * 8,
                                 yc + g2of[k], ssz[k]);
        yc += PLANE / 2;
    }
    cp_commit();
    #pragma unroll
    for (int cc = 0; cc < CPB; cc++) { xv[cc] = __ldg(xp); xp += PLANE / 4; }
    cp_wait0();
    __syncthreads();

    // ================= group loop: 64 iterations of 4 channels =================
    #pragma unroll 1
    for (int g = 0; g < NGRP; g++) {
        const int buf = g & 1;
        const bool pf = (g + 1 < NGRP);

        float4 xn[CPB];
        // issue staging + x loads for next group (consumed after the barrier)
        if (pf) {
            #pragma unroll
            for (int cc = 0; cc < CPB; cc++) {
                unsigned dbase = smem_u32(&sy[buf ^ 1][cc][0]);
                #pragma unroll
                for (int k = 0; k < NSLOT; k++)
                    if (wr[k]) cp_async8(dbase + (unsigned)(tid + k * NTHREADS) * 8,
                                         yc + g2of[k], ssz[k]);
                yc += PLANE / 2;
            }
            cp_commit();
            #pragma unroll
            for (int cc = 0; cc < CPB; cc++) { xn[cc] = __ldg(xp); xp += PLANE / 4; }
        }

        // ---- compute 4 channels from sy[buf]
        #pragma unroll
        for (int cc = 0; cc < CPB; cc++) {
            const float4 xvc = xv[cc];
            sxx[0] = fmaf(xvc.x, xvc.x, sxx[0]);
            sxx[1] = fmaf(xvc.y, xvc.y, sxx[1]);
            sxx[2] = fmaf(xvc.z, xvc.z, sxx[2]);
            sxx[3] = fmaf(xvc.w, xvc.w, sxx[3]);

            const float* slab = sy[buf][cc];
            const float* base = slab + (ty + i0) * SMW + tx * 4;

            #pragma unroll
            for (int i = 0; i < 3; i++) {
                const float* row = base + i * SMW;
                float4 t0 = *reinterpret_cast<const float4*>(row);
                float4 t1 = *reinterpret_cast<const float4*>(row + 4);
                float4 t2 = *reinterpret_cast<const float4*>(row + 8);
                float yr[12];
                yr[0] = t0.x; yr[1]  = t0.y; yr[2]  = t0.z; yr[3]  = t0.w;
                yr[4] = t1.x; yr[5]  = t1.y; yr[6]  = t1.z; yr[7]  = t1.w;
                yr[8] = t2.x; yr[9]  = t2.y; yr[10] = t2.z; yr[11] = t2.w;
                #pragma unroll
                for (int j = 0; j < 7; j++) {
                    acc[i][j][0] = fmaf(xvc.x, yr[j + 1], acc[i][j][0]);
                    acc[i][j][1] = fmaf(xvc.y, yr[j + 2], acc[i][j][1]);
                    acc[i][j][2] = fmaf(xvc.z, yr[j + 3], acc[i][j][2]);
                    acc[i][j][3] = fmaf(xvc.w, yr[j + 4], acc[i][j][3]);
                }
            }
            if (grp == 0) {   // warp-uniform (warps 0-1 vs 2-3)
                const float* row = base + 3 * SMW;
                float4 t0 = *reinterpret_cast<const float4*>(row);
                float4 t1 = *reinterpret_cast<const float4*>(row + 4);
                float4 t2 = *reinterpret_cast<const float4*>(row + 8);
                float yr[12];
                yr[0] = t0.x; yr[1]  = t0.y; yr[2]  = t0.z; yr[3]  = t0.w;
                yr[4] = t1.x; yr[5]  = t1.y; yr[6]  = t1.z; yr[7]  = t1.w;
                yr[8] = t2.x; yr[9]  = t2.y; yr[10] = t2.z; yr[11] = t2.w;
                #pragma unroll
                for (int j = 0; j < 7; j++) {
                    acc[3][j][0] = fmaf(xvc.x, yr[j + 1], acc[3][j][0]);
                    acc[3][j][1] = fmaf(xvc.y, yr[j + 2], acc[3][j][1]);
                    acc[3][j][2] = fmaf(xvc.z, yr[j + 3], acc[3][j][2]);
                    acc[3][j][3] = fmaf(xvc.w, yr[j + 4], acc[3][j][3]);
                }
            }

            // sum(y^2) readback of this thread's own staged slots (zeros where OOB)
            const float2* slab2 = reinterpret_cast<const float2*>(slab);
            #pragma unroll
            for (int k = 0; k < NSLOT; k++) {
                if (wr[k]) {
                    float2 v = slab2[tid + k * NTHREADS];
                    syy[k].x = fmaf(v.x, v.x, syy[k].x);
                    syy[k].y = fmaf(v.y, v.y, syy[k].y);
                }
            }
        }

        if (pf) {
            #pragma unroll
            for (int cc = 0; cc < CPB; cc++) xv[cc] = xn[cc];
        }
        cp_wait0();
        __syncthreads();
    }

    // ================= epilogue: normalize =================
    // publish per-halo-pixel sum(y^2) through slab (0,0)
    #pragma unroll
    for (int k = 0; k < NSLOT; k++)
        if (wr[k])
            reinterpret_cast<float2*>(sy[0][0])[tid + k * NTHREADS] = syy[k];
    __syncthreads();

    float invx[4];
    #pragma unroll
    for (int p = 0; p < 4; p++)
        invx[p] = 1.0f / fmaxf(sqrtf(sxx[p]), EPSF);

    const int nrows = grp ? 3 : 4;
    float* op = out + ((size_t)b * 49) * PLANE + (size_t)h * WW + w0 + tx * 4;
    #pragma unroll
    for (int i = 0; i < 4; i++) {
        if (i < nrows) {
            const int iglob = i0 + i;
            const float* row = sy[0][0] + (ty + iglob) * SMW + tx * 4;
            float inr[11];
            #pragma unroll
            for (int t = 1; t <= 10; t++)
                inr[t] = 1.0f / fmaxf(sqrtf(row[t]), EPSF);
            #pragma unroll
            for (int j = 0; j < 7; j++) {
                float4 o4;
                o4.x = acc[i][j][0] * invx[0] * inr[j + 1];
                o4.y = acc[i][j][1] * invx[1] * inr[j + 2];
                o4.z = acc[i][j][2] * invx[2] * inr[j + 3];
                o4.w = acc[i][j][3] * invx[3] * inr[j + 4];
                *reinterpret_cast<float4*>(op + (size_t)(iglob * 7 + j) * PLANE) = o4;
            }
        }
    }
}

extern "C" void kernel_launch(void* const* d_in, const int* in_sizes, int n_in,
                              void* d_out, int out_size) {
    const float* x = (const float*)d_in[0];
    const float* y = (const float*)d_in[1];
    float* out = (float*)d_out;
    int B = in_sizes[0] / (CCH * HH * WW);   // = 4
    dim3 grid(WW / TW, HH / TH, B);
    corr_kernel<<<grid, NTHREADS>>>(x, y, out);
}

// round 6
// speedup vs baseline: 4.8996x; 1.4686x over previous
#include <cuda_runtime.h>
#include <cstdint>

#define CCH 256
#define HH 256
#define WW 256
#define PLANE (HH * WW)
#define TH 8
#define TW 32
#define HALO_H 14                 // TH + 6
#define SMW 40                    // halo width in floats (8B-aligned window)
#define SMW2 (SMW / 2)            // 20 float2 per row
#define HALO_N2 (HALO_H * SMW2)   // 280 float2 per channel slab
#define SLAB (HALO_H * SMW)       // 560 floats per y slab
#define XSLAB (TH * TW)           // 256 floats per x slab
#define CPB 4                     // channels per barrier
#define NGRP (CCH / CPB)          // 64 groups
#define NSLOT 2                   // ceil(280 / 256) y staging slots per thread
#define NTHREADS 256
#define EPSF 1e-12f

__device__ __forceinline__ unsigned smem_u32(const void* p) {
    return (unsigned)__cvta_generic_to_shared(p);
}
__device__ __forceinline__ void cp_async8(unsigned dst, const void* src, unsigned sz) {
    asm volatile("cp.async.ca.shared.global [%0], [%1], 8, %2;\n"
                 :: "r"(dst), "l"(src), "r"(sz));
}
__device__ __forceinline__ void cp_async16(unsigned dst, const void* src) {
    asm volatile("cp.async.ca.shared.global [%0], [%1], 16;\n"
                 :: "r"(dst), "l"(src));
}
__device__ __forceinline__ void cp_commit() {
    asm volatile("cp.async.commit_group;\n");
}
__device__ __forceinline__ void cp_wait0() {
    asm volatile("cp.async.wait_group 0;\n");
}

__global__ __launch_bounds__(NTHREADS, 2)
void corr_kernel(const float* __restrict__ x,
                 const float* __restrict__ y,
                 float* __restrict__ out)
{
    __shared__ __align__(16) float sy[2][CPB][SLAB];
    __shared__ __align__(16) float sx[2][CPB][XSLAB];

    const int tid = threadIdx.x;
    const int tx  = tid & 7;          // 0..7, each owns 4 w-pixels
    const int ty  = (tid >> 3) & 7;   // 0..7
    const int grp = tid >> 6;         // 0..3: vertical offsets {0,1},{2,3},{4,5},{6}
    const int i0  = grp * 2 > 6 ? 6 : grp * 2;
    const bool two_rows = (grp < 3);
    const int b   = blockIdx.z;
    const int h0  = blockIdx.y * TH;
    const int w0  = blockIdx.x * TW;
    const int h   = h0 + ty;

    // ---- y staging slots: halo gy in [h0-3, h0+10], gx in [w0-4, w0+35], even gx
    int      g2of[NSLOT];
    unsigned ssz[NSLOT];
    bool     wr[NSLOT];
    #pragma unroll
    for (int k = 0; k < NSLOT; k++) {
        int li = tid + k * NTHREADS;
        int r  = li / SMW2;
        int c2 = li - r * SMW2;
        int gy = h0 - 3 + r;
        int gx = w0 - 4 + 2 * c2;
        wr[k]  = li < HALO_N2;
        bool v = wr[k] && gy >= 0 && gy < HH && gx >= 0 && gx < WW;
        g2of[k] = v ? (gy * (WW / 2) + (gx >> 1)) : 0;
        ssz[k]  = v ? 8u : 0u;
    }

    // ---- x staging slot: threads 0..63 each stage one float4 per channel
    const bool xstage = (tid < 64);
    const float* xsrc = x + (((size_t)b * CCH) * HH + h0 + (tid >> 3)) * WW
                          + w0 + (tid & 7) * 4;
    const float2* yc = reinterpret_cast<const float2*>(y) +
        (size_t)b * CCH * (PLANE / 2);

    float acc[2][7][4];
    #pragma unroll
    for (int i = 0; i < 2; i++)
        #pragma unroll
        for (int j = 0; j < 7; j++)
            #pragma unroll
            for (int p = 0; p < 4; p++)
                acc[i][j][p] = 0.f;

    float  sxx[4] = {0.f, 0.f, 0.f, 0.f};
    float2 syy[NSLOT];
    #pragma unroll
    for (int k = 0; k < NSLOT; k++) syy[k] = make_float2(0.f, 0.f);

    // ---- prologue: stage group 0 (channels 0..3) into buffer 0
    #pragma unroll
    for (int cc = 0; cc < CPB; cc++) {
        unsigned dy = smem_u32(&sy[0][cc][0]);
        #pragma unroll
        for (int k = 0; k < NSLOT; k++)
            if (wr[k]) cp_async8(dy + (unsigned)(tid + k * NTHREADS) * 8,
                                 yc + g2of[k], ssz[k]);
        yc += PLANE / 2;
        if (xstage)
            cp_async16(smem_u32(&sx[0][cc][0]) + (unsigned)tid * 16,
                       xsrc + (size_t)cc * PLANE);
    }
    cp_commit();
    cp_wait0();
    __syncthreads();

    // ================= group loop: 64 iterations of 4 channels =================
    #pragma unroll 1
    for (int g = 0; g < NGRP; g++) {
        const int buf = g & 1;
        const bool pf = (g + 1 < NGRP);

        // issue staging for next group (lands in buf^1; consumed after barrier)
        if (pf) {
            #pragma unroll
            for (int cc = 0; cc < CPB; cc++) {
                unsigned dy = smem_u32(&sy[buf ^ 1][cc][0]);
                #pragma unroll
                for (int k = 0; k < NSLOT; k++)
                    if (wr[k]) cp_async8(dy + (unsigned)(tid + k * NTHREADS) * 8,
                                         yc + g2of[k], ssz[k]);
                yc += PLANE / 2;
                if (xstage)
                    cp_async16(smem_u32(&sx[buf ^ 1][cc][0]) + (unsigned)tid * 16,
                               xsrc + (size_t)((g + 1) * CPB + cc) * PLANE);
            }
            cp_commit();
        }

        // ---- compute 4 channels from current buffers
        #pragma unroll
        for (int cc = 0; cc < CPB; cc++) {
            const float4 xvc = *reinterpret_cast<const float4*>(
                &sx[buf][cc][ty * TW + tx * 4]);
            sxx[0] = fmaf(xvc.x, xvc.x, sxx[0]);
            sxx[1] = fmaf(xvc.y, xvc.y, sxx[1]);
            sxx[2] = fmaf(xvc.z, xvc.z, sxx[2]);
            sxx[3] = fmaf(xvc.w, xvc.w, sxx[3]);

            const float* slab = sy[buf][cc];
            const float* base = slab + (ty + i0) * SMW + tx * 4;

            #pragma unroll
            for (int i = 0; i < 2; i++) {
                if (i == 0 || two_rows) {   // warp-uniform
                    const float* row = base + i * SMW;
                    float4 t0 = *reinterpret_cast<const float4*>(row);
                    float4 t1 = *reinterpret_cast<const float4*>(row + 4);
                    float4 t2 = *reinterpret_cast<const float4*>(row + 8);
                    float yr[12];
                    yr[0] = t0.x; yr[1]  = t0.y; yr[2]  = t0.z; yr[3]  = t0.w;
                    yr[4] = t1.x; yr[5]  = t1.y; yr[6]  = t1.z; yr[7]  = t1.w;
                    yr[8] = t2.x; yr[9]  = t2.y; yr[10] = t2.z; yr[11] = t2.w;
                    #pragma unroll
                    for (int j = 0; j < 7; j++) {
                        acc[i][j][0] = fmaf(xvc.x, yr[j + 1], acc[i][j][0]);
                        acc[i][j][1] = fmaf(xvc.y, yr[j + 2], acc[i][j][1]);
                        acc[i][j][2] = fmaf(xvc.z, yr[j + 3], acc[i][j][2]);
                        acc[i][j][3] = fmaf(xvc.w, yr[j + 4], acc[i][j][3]);
                    }
                }
            }

            // sum(y^2) readback of this thread's own staged slots (zeros where OOB)
            const float2* slab2 = reinterpret_cast<const float2*>(slab);
            #pragma unroll
            for (int k = 0; k < NSLOT; k++) {
                if (wr[k]) {
                    float2 v = slab2[tid + k * NTHREADS];
                    syy[k].x = fmaf(v.x, v.x, syy[k].x);
                    syy[k].y = fmaf(v.y, v.y, syy[k].y);
                }
            }
        }

        cp_wait0();
        __syncthreads();
    }

    // ================= epilogue: normalize =================
    // publish per-halo-pixel sum(y^2) through slab (0,0)
    #pragma unroll
    for (int k = 0; k < NSLOT; k++)
        if (wr[k])
            reinterpret_cast<float2*>(sy[0][0])[tid + k * NTHREADS] = syy[k];
    __syncthreads();

    float invx[4];
    #pragma unroll
    for (int p = 0; p < 4; p++)
        invx[p] = 1.0f / fmaxf(sqrtf(sxx[p]), EPSF);

    float* op = out + ((size_t)b * 49) * PLANE + (size_t)h * WW + w0 + tx * 4;
    #pragma unroll
    for (int i = 0; i < 2; i++) {
        if (i == 0 || two_rows) {
            const int iglob = i0 + i;
            const float* row = sy[0][0] + (ty + iglob) * SMW + tx * 4;
            float inr[11];
            #pragma unroll
            for (int t = 1; t <= 10; t++)
                inr[t] = 1.0f / fmaxf(sqrtf(row[t]), EPSF);
            #pragma unroll
            for (int j = 0; j < 7; j++) {
                float4 o4;
                o4.x = acc[i][j][0] * invx[0] * inr[j + 1];
                o4.y = acc[i][j][1] * invx[1] * inr[j + 2];
                o4.z = acc[i][j][2] * invx[2] * inr[j + 3];
                o4.w = acc[i][j][3] * invx[3] * inr[j + 4];
                *reinterpret_cast<float4*>(op + (size_t)(iglob * 7 + j) * PLANE) = o4;
            }
        }
    }
}

extern "C" void kernel_launch(void* const* d_in, const int* in_sizes, int n_in,
                              void* d_out, int out_size) {
    const float* x = (const float*)d_in[0];
    const float* y = (const float*)d_in[1];
    float* out = (float*)d_out;
    int B = in_sizes[0] / (CCH * HH * WW);   // = 4
    dim3 grid(WW / TW, HH / TH, B);
    corr_kernel<<<grid, NTHREADS>>>(x, y, out);
}

// round 7
// speedup vs baseline: 5.1317x; 1.0474x over previous
#include <cuda_runtime.h>
#include <cstdint>

#define CCH 256
#define HH 256
#define WW 256
#define PLANE (HH * WW)
#define TH 8
#define TW 32
#define HALO_ROWS 14              // TH + 6
#define HALO_W2 20                // staged float2 per row (40 floats)
#define HALO_N2 (HALO_ROWS * HALO_W2)  // 280 float2 per channel slab
#define SMW 44                    // y slab row stride in floats (conflict-free padding)
#define SMW2 (SMW / 2)            // 22 float2 stride
#define SLAB (HALO_ROWS * SMW)    // 616 floats per y slab
#define XROW 36                   // x slab row stride in floats (conflict-free padding)
#define XSLAB (TH * XROW)         // 288 floats per x slab
#define CPB 4                     // channels per barrier
#define NGRP (CCH / CPB)          // 64 groups
#define NSLOT 2                   // ceil(280 / 256) y staging slots per thread
#define NTHREADS 256
#define EPSF 1e-12f

__device__ __forceinline__ unsigned smem_u32(const void* p) {
    return (unsigned)__cvta_generic_to_shared(p);
}
__device__ __forceinline__ void cp_async8(unsigned dst, const void* src, unsigned sz) {
    asm volatile("cp.async.ca.shared.global [%0], [%1], 8, %2;\n"
                 :: "r"(dst), "l"(src), "r"(sz));
}
__device__ __forceinline__ void cp_async16(unsigned dst, const void* src) {
    asm volatile("cp.async.ca.shared.global [%0], [%1], 16;\n"
                 :: "r"(dst), "l"(src));
}
__device__ __forceinline__ void cp_commit() {
    asm volatile("cp.async.commit_group;\n");
}
__device__ __forceinline__ void cp_wait0() {
    asm volatile("cp.async.wait_group 0;\n");
}

__global__ __launch_bounds__(NTHREADS, 2)
void corr_kernel(const float* __restrict__ x,
                 const float* __restrict__ y,
                 float* __restrict__ out)
{
    __shared__ __align__(16) float sy[2][CPB][SLAB];
    __shared__ __align__(16) float sx[2][CPB][XSLAB];

    const int tid = threadIdx.x;
    const int tx  = tid & 3;          // 0..3, each owns 8 w-pixels
    const int ty  = (tid >> 2) & 7;   // 0..7
    const int grp = tid >> 5;         // 0..7: vertical offset index (7 = staging-only)
    const bool comp = (grp < 7);
    const int b   = blockIdx.z;
    const int h0  = blockIdx.y * TH;
    const int w0  = blockIdx.x * TW;
    const int h   = h0 + ty;

    // ---- y staging slots: halo gy in [h0-3, h0+10], gx in [w0-4, w0+35], even gx
    int      g2of[NSLOT];   // global float2 offset
    int      d2of[NSLOT];   // slab float2 offset (stride 22 float2 per row)
    unsigned ssz[NSLOT];
    bool     wr[NSLOT];
    #pragma unroll
    for (int k = 0; k < NSLOT; k++) {
        int li = tid + k * NTHREADS;
        int r  = li / HALO_W2;
        int c2 = li - r * HALO_W2;
        int gy = h0 - 3 + r;
        int gx = w0 - 4 + 2 * c2;
        wr[k]  = li < HALO_N2;
        bool v = wr[k] && gy >= 0 && gy < HH && gx >= 0 && gx < WW;
        g2of[k] = v ? (gy * (WW / 2) + (gx >> 1)) : 0;
        d2of[k] = r * SMW2 + c2;
        ssz[k]  = v ? 8u : 0u;
    }

    // ---- x staging: threads 0..63 stage one float4 per channel
    const bool xstage = (tid < 64);
    const unsigned xdst = (unsigned)((tid >> 3) * (XROW * 4) + (tid & 7) * 16);
    const float* xsrc = x + (((size_t)b * CCH) * HH + h0 + (tid >> 3)) * WW
                          + w0 + (tid & 7) * 4;
    const float2* yc = reinterpret_cast<const float2*>(y) +
        (size_t)b * CCH * (PLANE / 2);

    float acc[7][8];
    #pragma unroll
    for (int j = 0; j < 7; j++)
        #pragma unroll
        for (int p = 0; p < 8; p++)
            acc[j][p] = 0.f;

    float sxx[8];
    #pragma unroll
    for (int p = 0; p < 8; p++) sxx[p] = 0.f;
    float2 syy[NSLOT];
    #pragma unroll
    for (int k = 0; k < NSLOT; k++) syy[k] = make_float2(0.f, 0.f);

    // ---- prologue: stage group 0 (channels 0..3) into buffer 0
    #pragma unroll
    for (int cc = 0; cc < CPB; cc++) {
        unsigned dy = smem_u32(&sy[0][cc][0]);
        #pragma unroll
        for (int k = 0; k < NSLOT; k++)
            if (wr[k]) cp_async8(dy + (unsigned)d2of[k] * 8, yc + g2of[k], ssz[k]);
        yc += PLANE / 2;
        if (xstage)
            cp_async16(smem_u32(&sx[0][cc][0]) + xdst, xsrc + (size_t)cc * PLANE);
    }
    cp_commit();
    cp_wait0();
    __syncthreads();

    // ================= group loop: 64 iterations of 4 channels =================
    #pragma unroll 1
    for (int g = 0; g < NGRP; g++) {
        const int buf = g & 1;
        const bool pf = (g + 1 < NGRP);

        if (pf) {
            #pragma unroll
            for (int cc = 0; cc < CPB; cc++) {
                unsigned dy = smem_u32(&sy[buf ^ 1][cc][0]);
                #pragma unroll
                for (int k = 0; k < NSLOT; k++)
                    if (wr[k]) cp_async8(dy + (unsigned)d2of[k] * 8,
                                         yc + g2of[k], ssz[k]);
                yc += PLANE / 2;
                if (xstage)
                    cp_async16(smem_u32(&sx[buf ^ 1][cc][0]) + xdst,
                               xsrc + (size_t)((g + 1) * CPB + cc) * PLANE);
            }
            cp_commit();
        }

        // ---- compute 4 channels from current buffers
        #pragma unroll
        for (int cc = 0; cc < CPB; cc++) {
            if (comp) {   // warp-uniform (grp 7 warps skip)
                const float* xr = &sx[buf][cc][ty * XROW + tx * 8];
                float4 xa = *reinterpret_cast<const float4*>(xr);
                float4 xb = *reinterpret_cast<const float4*>(xr + 4);
                float xv[8] = {xa.x, xa.y, xa.z, xa.w, xb.x, xb.y, xb.z, xb.w};
                #pragma unroll
                for (int p = 0; p < 8; p++)
                    sxx[p] = fmaf(xv[p], xv[p], sxx[p]);

                const float* row = &sy[buf][cc][(ty + grp) * SMW + tx * 8];
                float4 t0 = *reinterpret_cast<const float4*>(row);
                float4 t1 = *reinterpret_cast<const float4*>(row + 4);
                float4 t2 = *reinterpret_cast<const float4*>(row + 8);
                float4 t3 = *reinterpret_cast<const float4*>(row + 12);
                float yr[16] = {t0.x, t0.y, t0.z, t0.w, t1.x, t1.y, t1.z, t1.w,
                                t2.x, t2.y, t2.z, t2.w, t3.x, t3.y, t3.z, t3.w};
                #pragma unroll
                for (int j = 0; j < 7; j++)
                    #pragma unroll
                    for (int p = 0; p < 8; p++)
                        acc[j][p] = fmaf(xv[p], yr[p + j + 1], acc[j][p]);
            }

            // sum(y^2) readback of this thread's own staged slots (zeros where OOB)
            const float2* slab2 = reinterpret_cast<const float2*>(&sy[buf][cc][0]);
            #pragma unroll
            for (int k = 0; k < NSLOT; k++) {
                if (wr[k]) {
                    float2 v = slab2[d2of[k]];
                    syy[k].x = fmaf(v.x, v.x, syy[k].x);
                    syy[k].y = fmaf(v.y, v.y, syy[k].y);
                }
            }
        }

        cp_wait0();
        __syncthreads();
    }

    // ================= epilogue: normalize =================
    // publish per-halo-pixel sum(y^2) through slab (0,0)
    #pragma unroll
    for (int k = 0; k < NSLOT; k++)
        if (wr[k])
            reinterpret_cast<float2*>(&sy[0][0][0])[d2of[k]] = syy[k];
    __syncthreads();

    if (comp) {
        float invx[8];
        #pragma unroll
        for (int p = 0; p < 8; p++)
            invx[p] = 1.0f / fmaxf(sqrtf(sxx[p]), EPSF);

        const float* row = &sy[0][0][(ty + grp) * SMW + tx * 8];
        float inr[15];
        #pragma unroll
        for (int t = 1; t <= 14; t++)
            inr[t] = 1.0f / fmaxf(sqrtf(row[t]), EPSF);

        float* op = out + ((size_t)b * 49 + grp * 7) * PLANE
                        + (size_t)h * WW + w0 + tx * 8;
        #pragma unroll
        for (int j = 0; j < 7; j++) {
            float4 oa, ob;
            oa.x = acc[j][0] * invx[0] * inr[j + 1];
            oa.y = acc[j][1] * invx[1] * inr[j + 2];
            oa.z = acc[j][2] * invx[2] * inr[j + 3];
            oa.w = acc[j][3] * invx[3] * inr[j + 4];
            ob.x = acc[j][4] * invx[4] * inr[j + 5];
            ob.y = acc[j][5] * invx[5] * inr[j + 6];
            ob.z = acc[j][6] * invx[6] * inr[j + 7];
            ob.w = acc[j][7] * invx[7] * inr[j + 8];
            *reinterpret_cast<float4*>(op + (size_t)j * PLANE)     = oa;
            *reinterpret_cast<float4*>(op + (size_t)j * PLANE + 4) = ob;
        }
    }
}

extern "C" void kernel_launch(void* const* d_in, const int* in_sizes, int n_in,
                              void* d_out, int out_size) {
    const float* x = (const float*)d_in[0];
    const float* y = (const float*)d_in[1];
    float* out = (float*)d_out;
    int B = in_sizes[0] / (CCH * HH * WW);   // = 4
    dim3 grid(WW / TW, HH / TH, B);
    corr_kernel<<<grid, NTHREADS>>>(x, y, out);
}